// round 7
// baseline (speedup 1.0000x reference)
#include <cuda_runtime.h>
#include <cuda_bf16.h>

#define B_   8
#define N_   1024
#define IN_  512
#define H_   8
#define SUP_ 64
#define BH_  (B_*H_)      // 64
#define ROWS_ (B_*N_)     // 8192

// Scratch (no cudaMalloc allowed). float4-typed for guaranteed 16B alignment.
__device__ float4 g_inputsv[BH_ * N_ * SUP_ / 4];   // [bh][n][o] 16.8 MB
__device__ float4 g_s4[BH_ * N_];                   // {s, e^s, e^{0.01s}, 0}
__device__ float4 g_t4[BH_ * N_];                   // {t, e^t, e^{0.01t}, 0}

// ---------- f32x2 helpers ----------
__device__ __forceinline__ unsigned long long pack2(float x, float y){
    unsigned long long r;
    asm("mov.b64 %0, {%1, %2};" : "=l"(r) : "f"(x), "f"(y));
    return r;
}
__device__ __forceinline__ void fma2(unsigned long long &d, unsigned long long a, unsigned long long b){
    asm("fma.rn.f32x2 %0, %1, %2, %0;" : "+l"(d) : "l"(a), "l"(b));
}
__device__ __forceinline__ float2 unpack2(unsigned long long v){
    float2 f;
    asm("mov.b64 {%0, %1}, %2;" : "=f"(f.x), "=f"(f.y) : "l"(v));
    return f;
}

// ---------- polynomial exp (used only in fc kernel now: 262K calls) ----------
__device__ __forceinline__ float fast_exp(float x){
    float t = x * 1.4426950408889634f;
    t = fmaxf(t, -80.0f);
    float r = t + 12582912.0f;               // round-to-nearest via magic
    float f = t - (r - 12582912.0f);
    int   n = __float_as_int(r) - 0x4B400000;
    float p = 1.33335581e-3f;
    p = fmaf(p, f, 9.61812911e-3f);
    p = fmaf(p, f, 5.55041087e-2f);
    p = fmaf(p, f, 2.40226507e-1f);
    p = fmaf(p, f, 6.93147181e-1f);
    p = fmaf(p, f, 1.0f);
    return __int_as_float(__float_as_int(p) + (n << 23));
}

// ============================================================
// Kernel A: per-head projection  inputs[bh][n][o] = X[b,n,:] @ W[h,:,o]
// CTA: 128 rows x 64 cols (one head), 128 threads, 16x4 per thread,
// Xs stored k-major so row-pair A operands load directly as u64 (no packs).
// ============================================================
__global__ __launch_bounds__(128) void proj_kernel(const float* __restrict__ X,
                                                   const float* __restrict__ W){
    __shared__ __align__(16) float Xs[32 * 132];   // [k][row], stride 132
    __shared__ __align__(16) float Ws[32 * 72];    // [k][col], stride 72

    const int h    = blockIdx.y;
    const int R0   = blockIdx.x * 128;
    const int tid  = threadIdx.x;
    const int rowg = tid >> 4;        // 0..7
    const int colg = tid & 15;        // 0..15
    const int r0   = rowg * 16;
    const int c0   = colg * 4;

    unsigned long long acc[8][4];     // 8 row-pairs x 4 cols
#pragma unroll
    for (int p = 0; p < 8; p++)
#pragma unroll
        for (int c = 0; c < 4; c++) acc[p][c] = 0ull;

    const float* Wh   = W + (size_t)h * (IN_ * SUP_);
    const float* Xrow = X + (size_t)(R0 + tid) * IN_;

    for (int kt = 0; kt < IN_; kt += 32){
        __syncthreads();
        // stage X transposed: thread = row tid
#pragma unroll
        for (int q = 0; q < 8; q++){
            float4 v = *(const float4*)(Xrow + kt + q * 4);
            Xs[(q * 4 + 0) * 132 + tid] = v.x;
            Xs[(q * 4 + 1) * 132 + tid] = v.y;
            Xs[(q * 4 + 2) * 132 + tid] = v.z;
            Xs[(q * 4 + 3) * 132 + tid] = v.w;
        }
        // stage W: k = tid>>4 (+8p), c = (tid&15)*4
        {
            int kk = tid >> 4, cc = (tid & 15) * 4;
#pragma unroll
            for (int p = 0; p < 4; p++){
                float4 v = *(const float4*)(Wh + (size_t)(kt + kk + p * 8) * SUP_ + cc);
                *(float4*)&Ws[(kk + p * 8) * 72 + cc] = v;
            }
        }
        __syncthreads();

#pragma unroll 8
        for (int k = 0; k < 32; k++){
            const float* xk = &Xs[k * 132 + r0];
            ulonglong2 a01 = *(const ulonglong2*)(xk);
            ulonglong2 a23 = *(const ulonglong2*)(xk + 4);
            ulonglong2 a45 = *(const ulonglong2*)(xk + 8);
            ulonglong2 a67 = *(const ulonglong2*)(xk + 12);
            float4 wv = *(const float4*)&Ws[k * 72 + c0];
            unsigned long long wb0 = pack2(wv.x, wv.x);
            unsigned long long wb1 = pack2(wv.y, wv.y);
            unsigned long long wb2 = pack2(wv.z, wv.z);
            unsigned long long wb3 = pack2(wv.w, wv.w);
            unsigned long long av[8] = {a01.x, a01.y, a23.x, a23.y, a45.x, a45.y, a67.x, a67.y};
#pragma unroll
            for (int p = 0; p < 8; p++){
                fma2(acc[p][0], av[p], wb0);
                fma2(acc[p][1], av[p], wb1);
                fma2(acc[p][2], av[p], wb2);
                fma2(acc[p][3], av[p], wb3);
            }
        }
    }

    // epilogue: each u64 = {row 2p, row 2p+1} at one col
    float* gi = (float*)g_inputsv;
#pragma unroll
    for (int p = 0; p < 8; p++){
        int R = R0 + r0 + 2 * p;
        int b = R >> 10, n = R & 1023;
        float2 v0 = unpack2(acc[p][0]);
        float2 v1 = unpack2(acc[p][1]);
        float2 v2 = unpack2(acc[p][2]);
        float2 v3 = unpack2(acc[p][3]);
        float* dst = gi + ((size_t)(b * H_ + h) * N_ + n) * SUP_ + c0;
        *(float4*)dst        = make_float4(v0.x, v1.x, v2.x, v3.x);
        *(float4*)(dst + 64) = make_float4(v0.y, v1.y, v2.y, v3.y);
    }
}

// ============================================================
// Kernel B: s/t logit pieces + factored exponentials
// ============================================================
__global__ __launch_bounds__(256) void fc_kernel(const float* __restrict__ w1, const float* __restrict__ b1,
                                                 const float* __restrict__ w2, const float* __restrict__ b2){
    int rid  = blockIdx.x * 8 + (threadIdx.x >> 5);   // 0..65535
    int lane = threadIdx.x & 31;
    int h    = (rid >> 10) & 7;
    const float* row = (const float*)g_inputsv + (size_t)rid * 64;
    float v0 = row[lane], v1 = row[lane + 32];
    float d1 = v0 * w1[h * 64 + lane] + v1 * w1[h * 64 + 32 + lane];
    float d2 = v0 * w2[h * 64 + lane] + v1 * w2[h * 64 + 32 + lane];
#pragma unroll
    for (int off = 16; off >= 1; off >>= 1){
        d1 += __shfl_xor_sync(0xffffffffu, d1, off);
        d2 += __shfl_xor_sync(0xffffffffu, d2, off);
    }
    if (lane == 0){
        float s = d1 + b1[h];
        float t = d2 + b2[h];
        g_s4[rid] = make_float4(s, fast_exp(s), fast_exp(0.01f * s), 0.f);
        g_t4[rid] = make_float4(t, fast_exp(t), fast_exp(0.01f * t), 0.f);
    }
}

// ============================================================
// Kernel C: fused masked-softmax attention + aggregation + relu
// CTA = one (b,h) x 64 rows; warp = 8 rows; 4 m-groups of 8 lanes;
// thread accumulates 8 rows x 8 cols (cols lx*4..+3 and 32+lx*4..+3)
// ============================================================
__global__ __launch_bounds__(256) void attn_kernel(const float* __restrict__ A,
                                                   float* __restrict__ out){
    __shared__ __align__(16) float  in_s[64 * 64];   // 16 KB m-tile of inputs[bh]
    __shared__ __align__(16) float4 t4_s[64];        // 1 KB {t, et, et2}

    const int bh   = blockIdx.y;
    const int b    = bh >> 3, h = bh & 7;
    const int tid  = threadIdx.x;
    const int w    = tid >> 5, lane = tid & 31;
    const int mg   = lane >> 3;        // m-group 0..3
    const int lx   = lane & 7;         // row-within-warp / col-group
    const int rbase = blockIdx.x * 64 + w * 8;

    const float4 srow = g_s4[(size_t)bh * N_ + rbase + lx];
    const float  thr  = -srow.x;       // l >= 0  <=>  t >= -s
    const float  es   = srow.y, es2 = srow.z;

    const float*  aptr   = A + ((size_t)b * N_ + rbase + lx) * N_ + mg;
    const float*  inbase = (const float*)g_inputsv + (size_t)bh * (N_ * SUP_);
    const float4* t4g    = g_t4 + (size_t)bh * N_;

    unsigned long long acc[8][4];
#pragma unroll
    for (int i = 0; i < 8; i++)
#pragma unroll
        for (int c = 0; c < 4; c++) acc[i][c] = 0ull;
    float lsum = 0.f;

    for (int mt = 0; mt < N_; mt += 64){
        __syncthreads();
        {   // stage inputs m-tile (contiguous 16 KB) + t4 slice
            const float4* src = (const float4*)inbase + (size_t)mt * 16;
            float4*       dst = (float4*)in_s;
#pragma unroll
            for (int j = 0; j < 4; j++) dst[tid + j * 256] = src[tid + j * 256];
            if (tid < 64) t4_s[tid] = t4g[mt + tid];
        }
        __syncthreads();

        const float* ap = aptr + mt;
#pragma unroll 4
        for (int t = 0; t < 16; t++){
            const int mm = t * 4 + mg;
            float4 tv = t4_s[mm];
            float  a  = ap[t * 4];                       // A in {0,1}
            float  e  = (tv.x >= thr) ? (es * tv.y) : (es2 * tv.z);
            e *= a;
            lsum += e;
            const float* xr = in_s + mm * 64 + lx * 4;
            ulonglong2 X0 = *(const ulonglong2*)xr;        // cols lx*4..+3
            ulonglong2 X1 = *(const ulonglong2*)(xr + 32); // cols 32+lx*4..+3
#pragma unroll
            for (int i = 0; i < 8; i++){
                float ei = __shfl_sync(0xffffffffu, e, (lane & 24) + i);
                unsigned long long ee = pack2(ei, ei);
                fma2(acc[i][0], ee, X0.x);
                fma2(acc[i][1], ee, X0.y);
                fma2(acc[i][2], ee, X1.x);
                fma2(acc[i][3], ee, X1.y);
            }
        }
    }

    // denominator: reduce each row's partial sum across the 4 m-groups
    lsum += __shfl_xor_sync(0xffffffffu, lsum, 8);
    lsum += __shfl_xor_sync(0xffffffffu, lsum, 16);
    // now lane (mg,lx) holds the full denominator of row lx

#pragma unroll
    for (int i = 0; i < 8; i++){
        float f[8];
#pragma unroll
        for (int c = 0; c < 4; c++){
            float2 v = unpack2(acc[i][c]);
            f[2 * c] = v.x; f[2 * c + 1] = v.y;
        }
#pragma unroll
        for (int j = 0; j < 8; j++){
            f[j] += __shfl_xor_sync(0xffffffffu, f[j], 8);
            f[j] += __shfl_xor_sync(0xffffffffu, f[j], 16);
        }
        float rs = __shfl_sync(0xffffffffu, lsum, (lane & 24) + i);  // denom of row i
        if ((i & 3) == mg){
            float inv = 1.0f / rs;
            float* op = out + ((size_t)(b * N_ + rbase + i)) * (H_ * SUP_) + h * SUP_ + lx * 4;
            *(float4*)op = make_float4(fmaxf(f[0], 0.f) * inv, fmaxf(f[1], 0.f) * inv,
                                       fmaxf(f[2], 0.f) * inv, fmaxf(f[3], 0.f) * inv);
            *(float4*)(op + 32) = make_float4(fmaxf(f[4], 0.f) * inv, fmaxf(f[5], 0.f) * inv,
                                              fmaxf(f[6], 0.f) * inv, fmaxf(f[7], 0.f) * inv);
        }
    }
}

// ============================================================
extern "C" void kernel_launch(void* const* d_in, const int* in_sizes, int n_in,
                              void* d_out, int out_size){
    // match inputs by element count: A=8388608, X=4194304, W=262144, w1/w2=512, b1/b2=8
    const float *A = nullptr, *X = nullptr, *W = nullptr;
    const float *w1 = nullptr, *w2 = nullptr, *b1 = nullptr, *b2 = nullptr;
    for (int i = 0; i < n_in; i++){
        const float* p = (const float*)d_in[i];
        switch (in_sizes[i]){
            case 8388608: A = p; break;
            case 4194304: X = p; break;
            case 262144:  W = p; break;
            case 512:     (w1 ? w2 : w1) = p; break;
            case 8:       (b1 ? b2 : b1) = p; break;
            default: break;
        }
    }
    float* out = (float*)d_out;

    proj_kernel<<<dim3(ROWS_ / 128, H_), 128>>>(X, W);
    fc_kernel<<<BH_ * N_ / 8, 256>>>(w1, b1, w2, b2);
    attn_kernel<<<dim3(N_ / 64, BH_), 256>>>(A, out);
}

// round 8
// speedup vs baseline: 1.6086x; 1.6086x over previous
#include <cuda_runtime.h>
#include <cuda_bf16.h>

#define B_   8
#define N_   1024
#define IN_  512
#define H_   8
#define SUP_ 64
#define BH_  (B_*H_)      // 64
#define ROWS_ (B_*N_)     // 8192

// Scratch (no cudaMalloc allowed). float4-typed for guaranteed 16B alignment.
__device__ float4 g_inputsv[BH_ * N_ * SUP_ / 4];   // [bh][n][o] 16.8 MB
__device__ float4 g_s4[BH_ * N_];                   // {s, e^s, e^{0.01s}, 0}
__device__ float4 g_t4[BH_ * N_];                   // {t, e^t, e^{0.01t}, 0}

// ---------- f32x2 helpers ----------
__device__ __forceinline__ unsigned long long pack2(float x, float y){
    unsigned long long r;
    asm("mov.b64 %0, {%1, %2};" : "=l"(r) : "f"(x), "f"(y));
    return r;
}
__device__ __forceinline__ void fma2(unsigned long long &d, unsigned long long a, unsigned long long b){
    asm("fma.rn.f32x2 %0, %1, %2, %0;" : "+l"(d) : "l"(a), "l"(b));
}
__device__ __forceinline__ float2 unpack2(unsigned long long v){
    float2 f;
    asm("mov.b64 {%0, %1}, %2;" : "=f"(f.x), "=f"(f.y) : "l"(v));
    return f;
}

// ---------- polynomial exp (only 262K calls, in fc kernel) ----------
__device__ __forceinline__ float fast_exp(float x){
    float t = x * 1.4426950408889634f;
    t = fmaxf(t, -80.0f);
    float r = t + 12582912.0f;               // round-to-nearest via magic
    float f = t - (r - 12582912.0f);
    int   n = __float_as_int(r) - 0x4B400000;
    float p = 1.33335581e-3f;
    p = fmaf(p, f, 9.61812911e-3f);
    p = fmaf(p, f, 5.55041087e-2f);
    p = fmaf(p, f, 2.40226507e-1f);
    p = fmaf(p, f, 6.93147181e-1f);
    p = fmaf(p, f, 1.0f);
    return __int_as_float(__float_as_int(p) + (n << 23));
}

// Ws column offset swizzle: shift upper 32-col half by 4 floats so the 8
// 16-byte chunks of each LDS.128 phase land on all 32 distinct banks.
#define WOFF(c) ((c) + (((c) >> 5) << 2))

// ============================================================
// Kernel A: per-head projection  inputs[bh][n][o] = X[b,n,:] @ W[h,:,o]
// CTA: 128 rows x 64 cols (one head), 256 threads, 4 rows x 8 cols/thread,
// cols-in-u64 accumulators (16 u64).
// ============================================================
__global__ __launch_bounds__(256) void proj_kernel(const float* __restrict__ X,
                                                   const float* __restrict__ W){
    __shared__ __align__(16) float Xs[128 * 36];   // [row][k], stride 36
    __shared__ __align__(16) float Ws[32 * 72];    // [k][swizzled col], stride 72

    const int h   = blockIdx.y;
    const int R0  = blockIdx.x * 128;
    const int tid = threadIdx.x;
    const int tx  = tid & 7,  ty = tid >> 3;       // 8 col-groups x 32 row-groups
    const int c0  = tx * 8,   r0 = ty * 4;
    const int wo  = WOFF(c0);

    unsigned long long acc[4][4];                  // [row i][col-pair c]
#pragma unroll
    for (int i = 0; i < 4; i++)
#pragma unroll
        for (int c = 0; c < 4; c++) acc[i][c] = 0ull;

    const float* Wh = W + (size_t)h * (IN_ * SUP_);

    for (int kt = 0; kt < IN_; kt += 32){
        __syncthreads();
        // stage X: 128 rows x 32 k  (4 float4 per thread, coalesced)
#pragma unroll
        for (int j = 0; j < 4; j++){
            int fid = tid + j * 256;
            int row = fid >> 3, kq = fid & 7;
            float4 v = *(const float4*)(X + (size_t)(R0 + row) * IN_ + kt + kq * 4);
            *(float4*)&Xs[row * 36 + kq * 4] = v;
        }
        // stage W: 32 k x 64 cols (2 float4 per thread), swizzled col offset
#pragma unroll
        for (int j = 0; j < 2; j++){
            int fid = tid + j * 256;
            int kk = fid >> 4, cc = (fid & 15) * 4;
            float4 v = *(const float4*)(Wh + (size_t)(kt + kk) * SUP_ + cc);
            *(float4*)&Ws[kk * 72 + WOFF(cc)] = v;
        }
        __syncthreads();

#pragma unroll 8
        for (int k = 0; k < 32; k++){
            const float* wk = &Ws[k * 72 + wo];
            ulonglong2 w0 = *(const ulonglong2*)(wk);       // cols c0..c0+3
            ulonglong2 w1 = *(const ulonglong2*)(wk + 4);   // cols c0+4..c0+7
#pragma unroll
            for (int i = 0; i < 4; i++){
                float a = Xs[(r0 + i) * 36 + k];
                unsigned long long aa = pack2(a, a);
                fma2(acc[i][0], aa, w0.x);
                fma2(acc[i][1], aa, w0.y);
                fma2(acc[i][2], aa, w1.x);
                fma2(acc[i][3], aa, w1.y);
            }
        }
    }

    float* gi = (float*)g_inputsv;
#pragma unroll
    for (int i = 0; i < 4; i++){
        int R = R0 + r0 + i;
        int b = R >> 10, n = R & 1023;
        float2 v0 = unpack2(acc[i][0]);
        float2 v1 = unpack2(acc[i][1]);
        float2 v2 = unpack2(acc[i][2]);
        float2 v3 = unpack2(acc[i][3]);
        float* dst = gi + ((size_t)(b * H_ + h) * N_ + n) * SUP_ + c0;
        *(float4*)dst       = make_float4(v0.x, v0.y, v1.x, v1.y);
        *(float4*)(dst + 4) = make_float4(v2.x, v2.y, v3.x, v3.y);
    }
}

// ============================================================
// Kernel B: s/t logit pieces + factored exponentials
// ============================================================
__global__ __launch_bounds__(256) void fc_kernel(const float* __restrict__ w1, const float* __restrict__ b1,
                                                 const float* __restrict__ w2, const float* __restrict__ b2){
    int rid  = blockIdx.x * 8 + (threadIdx.x >> 5);   // 0..65535
    int lane = threadIdx.x & 31;
    int h    = (rid >> 10) & 7;
    const float* row = (const float*)g_inputsv + (size_t)rid * 64;
    float v0 = row[lane], v1 = row[lane + 32];
    float d1 = v0 * w1[h * 64 + lane] + v1 * w1[h * 64 + 32 + lane];
    float d2 = v0 * w2[h * 64 + lane] + v1 * w2[h * 64 + 32 + lane];
#pragma unroll
    for (int off = 16; off >= 1; off >>= 1){
        d1 += __shfl_xor_sync(0xffffffffu, d1, off);
        d2 += __shfl_xor_sync(0xffffffffu, d2, off);
    }
    if (lane == 0){
        float s = d1 + b1[h];
        float t = d2 + b2[h];
        g_s4[rid] = make_float4(s, fast_exp(s), fast_exp(0.01f * s), 0.f);
        g_t4[rid] = make_float4(t, fast_exp(t), fast_exp(0.01f * t), 0.f);
    }
}

// ============================================================
// Kernel C: fused masked-softmax attention + aggregation + relu
// CTA = one (b,h) x 128 rows, 256 threads.
// Per 32-m tile:  e-phase builds e_s[m][row] in smem (no shfl anywhere),
// fma phase: rows-in-u64, acc[4 rowpair][4 col] = 16 u64.
// Denominators: every thread sums over ALL m -> no cross-thread reduction.
// ============================================================
#define MT_ 32   // m-tile

__global__ __launch_bounds__(256) void attn_kernel(const float* __restrict__ A,
                                                   float* __restrict__ out){
    __shared__ __align__(16) float  in_s[MT_ * 64];     // 8 KB
    __shared__ __align__(16) float  e_s[MT_ * 130];     // 16.25 KB, stride 130 (even -> 8B-aligned pairs)
    __shared__ __align__(16) float4 s4_s[128];          // 2 KB
    __shared__ __align__(16) float4 t4_s[MT_];          // 0.5 KB
    __shared__ float denom_s[256];                      // 1 KB  [half][row]

    const int bh  = blockIdx.y;
    const int b   = bh >> 3, h = bh & 7;
    const int R0  = blockIdx.x * 128;
    const int tid = threadIdx.x;
    const int cg  = tid & 15;          // 16 col groups x 4 cols
    const int rg  = tid >> 4;          // 16 row groups x 8 rows
    const int c0  = cg * 4;
    const int rb  = rg * 8;

    // denom-pass identity (independent mapping)
    const int drow  = tid & 127;
    const int dhalf = tid >> 7;        // 0/1 -> m halves

    // stage s4 once
    if (tid < 128) s4_s[tid] = g_s4[(size_t)bh * N_ + R0 + tid];

    const float*  Ab     = A + ((size_t)b * N_ + R0) * N_;
    const float*  inbase = (const float*)g_inputsv + (size_t)bh * (N_ * SUP_);
    const float4* t4g    = g_t4 + (size_t)bh * N_;

    unsigned long long acc[4][4];
#pragma unroll
    for (int i = 0; i < 4; i++)
#pragma unroll
        for (int c = 0; c < 4; c++) acc[i][c] = 0ull;
    float dreg = 0.f;

    for (int mt = 0; mt < N_; mt += MT_){
        __syncthreads();   // protect in_s/e_s reuse; first iter also fences s4_s
        // stage inputs m-tile (32x64 = 512 float4) + t4 slice
        {
            const float4* src = (const float4*)inbase + (size_t)mt * 16;
            float4*       dst = (float4*)in_s;
            dst[tid]       = src[tid];
            dst[tid + 256] = src[tid + 256];
            if (tid < MT_) t4_s[tid] = t4g[mt + tid];
        }
        __syncthreads();

        // e-phase: 128 rows x 32 m, coalesced A loads (warp = one row, 32 m)
#pragma unroll
        for (int j = 0; j < 16; j++){
            int idx = tid + j * 256;
            int row = idx >> 5, m = idx & 31;
            float4 sr = s4_s[row];
            float4 tv = t4_s[m];
            float  a  = Ab[(size_t)row * N_ + mt + m];          // 0.0 or 1.0
            float  e  = (tv.x >= -sr.x) ? (sr.y * tv.y) : (sr.z * tv.z);
            e_s[m * 130 + row] = a * e;
        }
        __syncthreads();

        // denominator partials: thread owns (row=drow, m-half=dhalf)
        {
            const float* ep = e_s + dhalf * 16 * 130 + drow;
            float ds = 0.f;
#pragma unroll
            for (int m = 0; m < 16; m++) ds += ep[m * 130];
            dreg += ds;
        }

        // fma phase: rows-in-u64
#pragma unroll 4
        for (int m = 0; m < MT_; m++){
            const float* ep = e_s + m * 130 + rb;
            unsigned long long e0 = *(const unsigned long long*)(ep);
            unsigned long long e1 = *(const unsigned long long*)(ep + 2);
            unsigned long long e2 = *(const unsigned long long*)(ep + 4);
            unsigned long long e3 = *(const unsigned long long*)(ep + 6);
            float4 xv = *(const float4*)&in_s[m * 64 + c0];
            unsigned long long x0 = pack2(xv.x, xv.x);
            unsigned long long x1 = pack2(xv.y, xv.y);
            unsigned long long x2 = pack2(xv.z, xv.z);
            unsigned long long x3 = pack2(xv.w, xv.w);
            fma2(acc[0][0], e0, x0); fma2(acc[0][1], e0, x1);
            fma2(acc[0][2], e0, x2); fma2(acc[0][3], e0, x3);
            fma2(acc[1][0], e1, x0); fma2(acc[1][1], e1, x1);
            fma2(acc[1][2], e1, x2); fma2(acc[1][3], e1, x3);
            fma2(acc[2][0], e2, x0); fma2(acc[2][1], e2, x1);
            fma2(acc[2][2], e2, x2); fma2(acc[2][3], e2, x3);
            fma2(acc[3][0], e3, x0); fma2(acc[3][1], e3, x1);
            fma2(acc[3][2], e3, x2); fma2(acc[3][3], e3, x3);
        }
    }

    // publish denominator partials, combine halves
    denom_s[dhalf * 128 + drow] = dreg;
    __syncthreads();

#pragma unroll
    for (int i = 0; i < 4; i++){
        int r0 = rb + 2 * i;                       // local rows r0, r0+1
        float d0 = denom_s[r0]     + denom_s[128 + r0];
        float d1 = denom_s[r0 + 1] + denom_s[128 + r0 + 1];
        float inv0 = 1.0f / d0, inv1 = 1.0f / d1;
        float2 v0 = unpack2(acc[i][0]);
        float2 v1 = unpack2(acc[i][1]);
        float2 v2 = unpack2(acc[i][2]);
        float2 v3 = unpack2(acc[i][3]);
        float* op0 = out + ((size_t)(b * N_ + R0 + r0)) * (H_ * SUP_) + h * SUP_ + c0;
        float* op1 = op0 + (H_ * SUP_);
        *(float4*)op0 = make_float4(fmaxf(v0.x, 0.f) * inv0, fmaxf(v1.x, 0.f) * inv0,
                                    fmaxf(v2.x, 0.f) * inv0, fmaxf(v3.x, 0.f) * inv0);
        *(float4*)op1 = make_float4(fmaxf(v0.y, 0.f) * inv1, fmaxf(v1.y, 0.f) * inv1,
                                    fmaxf(v2.y, 0.f) * inv1, fmaxf(v3.y, 0.f) * inv1);
    }
}

// ============================================================
extern "C" void kernel_launch(void* const* d_in, const int* in_sizes, int n_in,
                              void* d_out, int out_size){
    // match inputs by element count: A=8388608, X=4194304, W=262144, w1/w2=512, b1/b2=8
    const float *A = nullptr, *X = nullptr, *W = nullptr;
    const float *w1 = nullptr, *w2 = nullptr, *b1 = nullptr, *b2 = nullptr;
    for (int i = 0; i < n_in; i++){
        const float* p = (const float*)d_in[i];
        switch (in_sizes[i]){
            case 8388608: A = p; break;
            case 4194304: X = p; break;
            case 262144:  W = p; break;
            case 512:     (w1 ? w2 : w1) = p; break;
            case 8:       (b1 ? b2 : b1) = p; break;
            default: break;
        }
    }
    float* out = (float*)d_out;

    proj_kernel<<<dim3(ROWS_ / 128, H_), 256>>>(X, W);
    fc_kernel<<<BH_ * N_ / 8, 256>>>(w1, b1, w2, b2);
    attn_kernel<<<dim3(N_ / 128, BH_), 256>>>(A, out);
}

// round 9
// speedup vs baseline: 1.9266x; 1.1977x over previous
#include <cuda_runtime.h>
#include <cuda_bf16.h>

#define B_   8
#define N_   1024
#define IN_  512
#define H_   8
#define SUP_ 64
#define BH_  (B_*H_)      // 64
#define ROWS_ (B_*N_)     // 8192

// Scratch (no cudaMalloc allowed). float4-typed for guaranteed 16B alignment.
__device__ float4 g_inputsv[BH_ * N_ * SUP_ / 4];   // [bh][n][o] 16.8 MB
__device__ float4 g_s4[BH_ * N_];                   // {s, e^s, e^{0.01s}, 0}
__device__ float4 g_t4[BH_ * N_];                   // {t, e^t, e^{0.01t}, 0}

// ---------- helpers ----------
__device__ __forceinline__ unsigned long long pack2(float x, float y){
    unsigned long long r;
    asm("mov.b64 %0, {%1, %2};" : "=l"(r) : "f"(x), "f"(y));
    return r;
}
__device__ __forceinline__ void fma2(unsigned long long &d, unsigned long long a, unsigned long long b){
    asm("fma.rn.f32x2 %0, %1, %2, %0;" : "+l"(d) : "l"(a), "l"(b));
}
__device__ __forceinline__ float2 unpack2(unsigned long long v){
    float2 f;
    asm("mov.b64 {%0, %1}, %2;" : "=f"(f.x), "=f"(f.y) : "l"(v));
    return f;
}
__device__ __forceinline__ unsigned smem_u32(const void* p){
    unsigned a;
    asm("{ .reg .u64 t; cvta.to.shared.u64 t, %1; cvt.u32.u64 %0, t; }" : "=r"(a) : "l"(p));
    return a;
}
__device__ __forceinline__ void cpa16(unsigned dst, const void* src){
    asm volatile("cp.async.cg.shared.global [%0], [%1], 16;" :: "r"(dst), "l"(src));
}
__device__ __forceinline__ void cpa_commit(){ asm volatile("cp.async.commit_group;"); }
__device__ __forceinline__ void cpa_wait0(){ asm volatile("cp.async.wait_group 0;"); }

// ---------- polynomial exp (only 262K calls, in fc kernel) ----------
__device__ __forceinline__ float fast_exp(float x){
    float t = x * 1.4426950408889634f;
    t = fmaxf(t, -80.0f);
    float r = t + 12582912.0f;               // round-to-nearest via magic
    float f = t - (r - 12582912.0f);
    int   n = __float_as_int(r) - 0x4B400000;
    float p = 1.33335581e-3f;
    p = fmaf(p, f, 9.61812911e-3f);
    p = fmaf(p, f, 5.55041087e-2f);
    p = fmaf(p, f, 2.40226507e-1f);
    p = fmaf(p, f, 6.93147181e-1f);
    p = fmaf(p, f, 1.0f);
    return __int_as_float(__float_as_int(p) + (n << 23));
}

// Ws column swizzle: shift upper 32-col half by 4 floats -> conflict-free LDS.128
#define WOFF(c) ((c) + (((c) >> 5) << 2))

#define XSTR 36
#define XS_TILE (128 * XSTR)       // floats per X buffer
#define WS_TILE (32 * 72)          // floats per W buffer
#define PROJ_SMEM ((2 * XS_TILE + 2 * WS_TILE) * 4)   // 55296 bytes

// ============================================================
// Kernel A: per-head projection  inputs[bh][n][o] = X[b,n,:] @ W[h,:,o]
// CTA: 128 rows x 64 cols, 256 threads, 4 rows x 8 cols/thread.
// cp.async double-buffered staging: one wait+sync per k-tile.
// ============================================================
__global__ __launch_bounds__(256, 4) void proj_kernel(const float* __restrict__ X,
                                                      const float* __restrict__ W){
    extern __shared__ __align__(16) float sm[];
    float* Xs = sm;                       // [2][128][XSTR]
    float* Ws = sm + 2 * XS_TILE;         // [2][32][72]

    const int h   = blockIdx.y;
    const int R0  = blockIdx.x * 128;
    const int tid = threadIdx.x;
    const int tx  = tid & 7,  ty = tid >> 3;
    const int c0  = tx * 8,   r0 = ty * 4;
    const int wo  = WOFF(c0);

    const float* Wh = W + (size_t)h * (IN_ * SUP_);

    // precomputed staging addresses
    const int xrow = tid >> 3, xkq = (tid & 7) * 4;
    const int wkk  = tid >> 4, wcc = (tid & 15) * 4;
    const unsigned xs_base = smem_u32(Xs);
    const unsigned ws_base = smem_u32(Ws);

    // stage(kt, p)
    auto stage = [&](int kt, int p){
        const float* xsrc = X + (size_t)(R0 + xrow) * IN_ + kt + xkq;
        unsigned     xdst = xs_base + (unsigned)(p * XS_TILE + xrow * XSTR + xkq) * 4u;
#pragma unroll
        for (int j = 0; j < 4; j++)
            cpa16(xdst + (unsigned)(j * 32 * XSTR) * 4u, xsrc + (size_t)(j * 32) * IN_);
        const float* wsrc = Wh + (size_t)(kt + wkk) * SUP_ + wcc;
        unsigned     wdst = ws_base + (unsigned)(p * WS_TILE + wkk * 72 + WOFF(wcc)) * 4u;
        cpa16(wdst, wsrc);
        cpa16(wdst + (unsigned)(16 * 72) * 4u, wsrc + (size_t)16 * SUP_);
        cpa_commit();
    };

    unsigned long long acc[4][4];
#pragma unroll
    for (int i = 0; i < 4; i++)
#pragma unroll
        for (int c = 0; c < 4; c++) acc[i][c] = 0ull;

    stage(0, 0);

    for (int t = 0; t < IN_ / 32; t++){
        const int p = t & 1;
        cpa_wait0();
        __syncthreads();
        if (t + 1 < IN_ / 32) stage((t + 1) * 32, p ^ 1);

        const float* Xp = Xs + p * XS_TILE;
        const float* Wp = Ws + p * WS_TILE;
#pragma unroll 8
        for (int k = 0; k < 32; k++){
            const float* wk = &Wp[k * 72 + wo];
            ulonglong2 w0 = *(const ulonglong2*)(wk);
            ulonglong2 w1 = *(const ulonglong2*)(wk + 4);
#pragma unroll
            for (int i = 0; i < 4; i++){
                float a = Xp[(r0 + i) * XSTR + k];
                unsigned long long aa = pack2(a, a);
                fma2(acc[i][0], aa, w0.x);
                fma2(acc[i][1], aa, w0.y);
                fma2(acc[i][2], aa, w1.x);
                fma2(acc[i][3], aa, w1.y);
            }
        }
    }

    float* gi = (float*)g_inputsv;
#pragma unroll
    for (int i = 0; i < 4; i++){
        int R = R0 + r0 + i;
        int b = R >> 10, n = R & 1023;
        float2 v0 = unpack2(acc[i][0]);
        float2 v1 = unpack2(acc[i][1]);
        float2 v2 = unpack2(acc[i][2]);
        float2 v3 = unpack2(acc[i][3]);
        float* dst = gi + ((size_t)(b * H_ + h) * N_ + n) * SUP_ + c0;
        *(float4*)dst       = make_float4(v0.x, v0.y, v1.x, v1.y);
        *(float4*)(dst + 4) = make_float4(v2.x, v2.y, v3.x, v3.y);
    }
}

// ============================================================
// Kernel B: s/t logit pieces + factored exponentials
// ============================================================
__global__ __launch_bounds__(256) void fc_kernel(const float* __restrict__ w1, const float* __restrict__ b1,
                                                 const float* __restrict__ w2, const float* __restrict__ b2){
    int rid  = blockIdx.x * 8 + (threadIdx.x >> 5);   // 0..65535
    int lane = threadIdx.x & 31;
    int h    = (rid >> 10) & 7;
    const float* row = (const float*)g_inputsv + (size_t)rid * 64;
    float v0 = row[lane], v1 = row[lane + 32];
    float d1 = v0 * w1[h * 64 + lane] + v1 * w1[h * 64 + 32 + lane];
    float d2 = v0 * w2[h * 64 + lane] + v1 * w2[h * 64 + 32 + lane];
#pragma unroll
    for (int off = 16; off >= 1; off >>= 1){
        d1 += __shfl_xor_sync(0xffffffffu, d1, off);
        d2 += __shfl_xor_sync(0xffffffffu, d2, off);
    }
    if (lane == 0){
        float s = d1 + b1[h];
        float t = d2 + b2[h];
        g_s4[rid] = make_float4(s, fast_exp(s), fast_exp(0.01f * s), 0.f);
        g_t4[rid] = make_float4(t, fast_exp(t), fast_exp(0.01f * t), 0.f);
    }
}

// ============================================================
// Kernel C: fused masked-softmax attention + aggregation + relu
// CTA = one (b,h) x 128 rows, 256 threads, forced 4 CTAs/SM.
// Double-buffered in_s/t4 staged by cp.async; e_s matrix per 32-m tile;
// rows-in-u64 fma phase (16 u64 acc); no shfl anywhere.
// ============================================================
#define MT_ 32   // m-tile

__global__ __launch_bounds__(256, 4) void attn_kernel(const float* __restrict__ A,
                                                      float* __restrict__ out){
    __shared__ __align__(16) float  in_s[2][MT_ * 64];  // 16 KB
    __shared__ __align__(16) float  e_s[MT_ * 130];     // 16.25 KB
    __shared__ __align__(16) float4 s4_s[128];          // 2 KB
    __shared__ __align__(16) float4 t4_s[2][MT_];       // 1 KB
    __shared__ float denom_s[256];                      // 1 KB

    const int bh  = blockIdx.y;
    const int b   = bh >> 3, h = bh & 7;
    const int R0  = blockIdx.x * 128;
    const int tid = threadIdx.x;
    const int cg  = tid & 15;          // 16 col groups x 4 cols
    const int rg  = tid >> 4;          // 16 row groups x 8 rows
    const int c0  = cg * 4;
    const int rb  = rg * 8;

    const int drow  = tid & 127;       // denom-pass identity
    const int dhalf = tid >> 7;

    // e-phase identity: 4 rows x 4 m per j-iter, float4 A loads
    const int erow0 = tid >> 3;        // 0..31 (+32j)
    const int em0   = (tid & 7) * 4;   // m base

    if (tid < 128) s4_s[tid] = g_s4[(size_t)bh * N_ + R0 + tid];

    const float*  Ab     = A + ((size_t)b * N_ + R0) * N_;
    const float*  inbase = (const float*)g_inputsv + (size_t)bh * (N_ * SUP_);
    const float4* t4g    = g_t4 + (size_t)bh * N_;

    const unsigned in_u  = smem_u32(in_s);
    const unsigned t4_u  = smem_u32(t4_s);

    auto stage = [&](int mt, int p){
        const float4* src = (const float4*)inbase + (size_t)mt * 16;
        unsigned dst = in_u + (unsigned)(p * MT_ * 64 + tid * 4) * 4u;
        cpa16(dst,                    src + tid);
        cpa16(dst + 256u * 16u,       src + tid + 256);
        if (tid < MT_) cpa16(t4_u + (unsigned)(p * MT_ + tid) * 16u, t4g + mt + tid);
        cpa_commit();
    };

    unsigned long long acc[4][4];
#pragma unroll
    for (int i = 0; i < 4; i++)
#pragma unroll
        for (int c = 0; c < 4; c++) acc[i][c] = 0ull;
    float dreg = 0.f;

    stage(0, 0);

    for (int t = 0; t < N_ / MT_; t++){
        const int p  = t & 1;
        const int mt = t * MT_;
        cpa_wait0();
        __syncthreads();                       // tile data ready; prev reads done
        if (t + 1 < N_ / MT_) stage(mt + MT_, p ^ 1);

        // e-phase: 128 rows x 32 m  (float4 A loads, coalesced)
#pragma unroll
        for (int j = 0; j < 4; j++){
            int row = erow0 + j * 32;
            float4 sr = s4_s[row];
            float4 a4 = *(const float4*)(Ab + (size_t)row * N_ + mt + em0);
            float4 t0 = t4_s[p][em0 + 0];
            float4 t1 = t4_s[p][em0 + 1];
            float4 t2 = t4_s[p][em0 + 2];
            float4 t3 = t4_s[p][em0 + 3];
            float thr = -sr.x;
            e_s[(em0 + 0) * 130 + row] = a4.x * ((t0.x >= thr) ? (sr.y * t0.y) : (sr.z * t0.z));
            e_s[(em0 + 1) * 130 + row] = a4.y * ((t1.x >= thr) ? (sr.y * t1.y) : (sr.z * t1.z));
            e_s[(em0 + 2) * 130 + row] = a4.z * ((t2.x >= thr) ? (sr.y * t2.y) : (sr.z * t2.z));
            e_s[(em0 + 3) * 130 + row] = a4.w * ((t3.x >= thr) ? (sr.y * t3.y) : (sr.z * t3.z));
        }
        __syncthreads();

        // denominator partials: thread owns (row=drow, m-half=dhalf)
        {
            const float* ep = e_s + dhalf * 16 * 130 + drow;
            float ds = 0.f;
#pragma unroll
            for (int m = 0; m < 16; m++) ds += ep[m * 130];
            dreg += ds;
        }

        // fma phase: rows-in-u64
        const float* inp = in_s[p];
#pragma unroll 4
        for (int m = 0; m < MT_; m++){
            const float* ep = e_s + m * 130 + rb;
            unsigned long long e0 = *(const unsigned long long*)(ep);
            unsigned long long e1 = *(const unsigned long long*)(ep + 2);
            unsigned long long e2 = *(const unsigned long long*)(ep + 4);
            unsigned long long e3 = *(const unsigned long long*)(ep + 6);
            float4 xv = *(const float4*)&inp[m * 64 + c0];
            unsigned long long x0 = pack2(xv.x, xv.x);
            unsigned long long x1 = pack2(xv.y, xv.y);
            unsigned long long x2 = pack2(xv.z, xv.z);
            unsigned long long x3 = pack2(xv.w, xv.w);
            fma2(acc[0][0], e0, x0); fma2(acc[0][1], e0, x1);
            fma2(acc[0][2], e0, x2); fma2(acc[0][3], e0, x3);
            fma2(acc[1][0], e1, x0); fma2(acc[1][1], e1, x1);
            fma2(acc[1][2], e1, x2); fma2(acc[1][3], e1, x3);
            fma2(acc[2][0], e2, x0); fma2(acc[2][1], e2, x1);
            fma2(acc[2][2], e2, x2); fma2(acc[2][3], e2, x3);
            fma2(acc[3][0], e3, x0); fma2(acc[3][1], e3, x1);
            fma2(acc[3][2], e3, x2); fma2(acc[3][3], e3, x3);
        }
    }

    denom_s[dhalf * 128 + drow] = dreg;
    __syncthreads();

#pragma unroll
    for (int i = 0; i < 4; i++){
        int r0 = rb + 2 * i;
        float d0 = denom_s[r0]     + denom_s[128 + r0];
        float d1 = denom_s[r0 + 1] + denom_s[128 + r0 + 1];
        float inv0 = 1.0f / d0, inv1 = 1.0f / d1;
        float2 v0 = unpack2(acc[i][0]);
        float2 v1 = unpack2(acc[i][1]);
        float2 v2 = unpack2(acc[i][2]);
        float2 v3 = unpack2(acc[i][3]);
        float* op0 = out + ((size_t)(b * N_ + R0 + r0)) * (H_ * SUP_) + h * SUP_ + c0;
        float* op1 = op0 + (H_ * SUP_);
        *(float4*)op0 = make_float4(fmaxf(v0.x, 0.f) * inv0, fmaxf(v1.x, 0.f) * inv0,
                                    fmaxf(v2.x, 0.f) * inv0, fmaxf(v3.x, 0.f) * inv0);
        *(float4*)op1 = make_float4(fmaxf(v0.y, 0.f) * inv1, fmaxf(v1.y, 0.f) * inv1,
                                    fmaxf(v2.y, 0.f) * inv1, fmaxf(v3.y, 0.f) * inv1);
    }
}

// ============================================================
extern "C" void kernel_launch(void* const* d_in, const int* in_sizes, int n_in,
                              void* d_out, int out_size){
    // match inputs by element count: A=8388608, X=4194304, W=262144, w1/w2=512, b1/b2=8
    const float *A = nullptr, *X = nullptr, *W = nullptr;
    const float *w1 = nullptr, *w2 = nullptr, *b1 = nullptr, *b2 = nullptr;
    for (int i = 0; i < n_in; i++){
        const float* p = (const float*)d_in[i];
        switch (in_sizes[i]){
            case 8388608: A = p; break;
            case 4194304: X = p; break;
            case 262144:  W = p; break;
            case 512:     (w1 ? w2 : w1) = p; break;
            case 8:       (b1 ? b2 : b1) = p; break;
            default: break;
        }
    }
    float* out = (float*)d_out;

    cudaFuncSetAttribute(proj_kernel, cudaFuncAttributeMaxDynamicSharedMemorySize, PROJ_SMEM);

    proj_kernel<<<dim3(ROWS_ / 128, H_), 256, PROJ_SMEM>>>(X, W);
    fc_kernel<<<BH_ * N_ / 8, 256>>>(w1, b1, w2, b2);
    attn_kernel<<<dim3(N_ / 128, BH_), 256>>>(A, out);
}